// round 10
// baseline (speedup 1.0000x reference)
#include <cuda_runtime.h>

// Problem constants
#define N_IMG 4
#define C_IN  256
#define C_MID 64
#define H     64
#define W     64
#define HW    4096
#define KK    25
#define MASK_STRIDE 116

// Scratch (device globals; no allocation allowed)
__device__ float g_comp[N_IMG * C_MID * HW];            // [n][oc][p]
__device__ float g_mask[N_IMG * HW * MASK_STRIDE];      // [n][p][ij*28+k]
__device__ float g_wenc[C_MID * 9 * 4 * 28];            // [(ic*9+tap)*4+ij][28k]

// ---------------------------------------------------------------------------
// Kernel 0: one-time transpose of w_enc into k2's smem layout.
// ---------------------------------------------------------------------------
__global__ void transpose_wenc_kernel(const float* __restrict__ w_enc) {
  int i = blockIdx.x * 256 + threadIdx.x;      // over 100*64*9 = 57600
  if (i >= 100 * 64 * 9) return;
  int tap = i % 9;
  int ic  = (i / 9) % 64;
  int e   = i / (9 * 64);
  int k   = e >> 2;
  int ij  = e & 3;
  g_wenc[((ic * 9 + tap) * 4 + ij) * 28 + k] = w_enc[i];
}

// ---------------------------------------------------------------------------
// Kernel 1 (v6, unchanged): 1x1 conv 256 -> 64.
// ---------------------------------------------------------------------------
#define WT_STR 36
#define K1_SMEM ((256 * WT_STR + 32 * 128) * 4)   // 53248 B

__global__ void __launch_bounds__(256) conv1x1_kernel(
    const float* __restrict__ x,
    const float* __restrict__ w_comp,
    const float* __restrict__ b_comp) {
  extern __shared__ float sm1[];
  float* wt = sm1;                  // [256][36]
  float* xs = sm1 + 256 * WT_STR;   // [32][128]

  int tid = threadIdx.x;
  int ocg = tid & 3;
  int pp  = tid >> 2;

  int b     = blockIdx.x;          // 256 blocks
  int oc0   = (b & 1) * 32;
  int gp0   = (b >> 1) * 128;
  int n     = gp0 >> 12;
  int pbase = gp0 & 4095;

  for (int i = tid; i < 256 * 32; i += 256) {
    int j = i >> 8;
    int c = i & 255;
    wt[c * WT_STR + j] = w_comp[(oc0 + j) * 256 + c];
  }

  const float* xb = x + (size_t)n * C_IN * HW + pbase;

  float acc[16];
  #pragma unroll
  for (int j = 0; j < 8; j++) {
    float bv = __ldg(b_comp + oc0 + ocg * 8 + j);
    acc[j] = bv; acc[8 + j] = bv;
  }

  for (int cc = 0; cc < 8; cc++) {
    __syncthreads();
    {
      int c   = tid >> 5;
      int px4 = (tid & 31) * 4;
      #pragma unroll
      for (int i2 = 0; i2 < 4; i2++) {
        int ch = c + i2 * 8;
        float4 v = *(const float4*)(xb + (cc * 32 + ch) * HW + px4);
        *(float4*)(xs + ch * 128 + px4) = v;
      }
    }
    __syncthreads();

    #pragma unroll 8
    for (int c = 0; c < 32; c++) {
      float xv0 = xs[c * 128 + 2 * pp];
      float xv1 = xs[c * 128 + 2 * pp + 1];
      const float4* wr =
          (const float4*)(wt + (cc * 32 + c) * WT_STR + ocg * 8);
      float4 w0 = wr[0], w1 = wr[1];
      acc[0]  += w0.x * xv0;  acc[8]  += w0.x * xv1;
      acc[1]  += w0.y * xv0;  acc[9]  += w0.y * xv1;
      acc[2]  += w0.z * xv0;  acc[10] += w0.z * xv1;
      acc[3]  += w0.w * xv0;  acc[11] += w0.w * xv1;
      acc[4]  += w1.x * xv0;  acc[12] += w1.x * xv1;
      acc[5]  += w1.y * xv0;  acc[13] += w1.y * xv1;
      acc[6]  += w1.z * xv0;  acc[14] += w1.z * xv1;
      acc[7]  += w1.w * xv0;  acc[15] += w1.w * xv1;
    }
  }

  float* ob = g_comp + ((size_t)n * C_MID + oc0 + ocg * 8) * HW + pbase + 2 * pp;
  #pragma unroll
  for (int j = 0; j < 8; j++)
    *(float2*)(ob + j * HW) = make_float2(acc[j], acc[8 + j]);
}

// ---------------------------------------------------------------------------
// Kernel 2 (v4, unchanged): 3x3 conv + pixel-shuffle softmax.
// ---------------------------------------------------------------------------
#define K2_ICC 16
#define CT_ROW 12
#define WS_FLOATS (K2_ICC * 9 * 4 * 28)      // 16128
#define CT_FLOATS (K2_ICC * 10 * CT_ROW)     // 1920

__global__ void __launch_bounds__(128) conv3x3_softmax_kernel(
    const float* __restrict__ b_enc) {
  extern __shared__ float sm[];
  float* ws = sm;
  float* ct = sm + WS_FLOATS;

  int tid = threadIdx.x;
  int ij  = tid & 3;
  int tp  = tid >> 2;
  int r   = tp >> 2;
  int c0  = (tp & 3) * 2;

  int b  = blockIdx.x;
  int n  = b >> 6;
  int t  = b & 63;
  int h0 = (t >> 3) * 8;
  int w0 = (t & 7) * 8;

  float acc0[25], acc1[25];
  #pragma unroll
  for (int k = 0; k < 25; k++) { acc0[k] = 0.f; acc1[k] = 0.f; }

  for (int icc = 0; icc < C_MID / K2_ICC; icc++) {
    int ic0 = icc * K2_ICC;
    {
      const float4* src = (const float4*)(g_wenc + icc * WS_FLOATS);
      float4* dst = (float4*)ws;
      for (int i = tid; i < WS_FLOATS / 4; i += 128) dst[i] = src[i];
    }
    for (int i = tid; i < CT_FLOATS; i += 128) {
      int xx  = i % CT_ROW;
      int yy  = (i / CT_ROW) % 10;
      int icl = i / (10 * CT_ROW);
      int gh = h0 - 1 + yy, gw = w0 - 1 + xx;
      float v = 0.f;
      if (gh >= 0 && gh < H && gw >= 0 && gw < W)
        v = g_comp[((size_t)(n * C_MID + ic0 + icl) << 12) + gh * W + gw];
      ct[(icl * 10 + yy) * CT_ROW + xx] = v;
    }
    __syncthreads();

    for (int icl = 0; icl < K2_ICC; icl++) {
      #pragma unroll
      for (int ty = 0; ty < 3; ty++) {
        #pragma unroll
        for (int tx = 0; tx < 3; tx++) {
          float cv0 = ct[(icl * 10 + r + ty) * CT_ROW + c0 + tx];
          float cv1 = ct[(icl * 10 + r + ty) * CT_ROW + c0 + 1 + tx];
          const float* wb = ws + ((icl * 9 + ty * 3 + tx) * 4 + ij) * 28;
          const float4* wb4 = (const float4*)wb;
          #pragma unroll
          for (int q = 0; q < 6; q++) {
            float4 w4 = wb4[q];
            acc0[q*4+0] += w4.x * cv0;  acc1[q*4+0] += w4.x * cv1;
            acc0[q*4+1] += w4.y * cv0;  acc1[q*4+1] += w4.y * cv1;
            acc0[q*4+2] += w4.z * cv0;  acc1[q*4+2] += w4.z * cv1;
            acc0[q*4+3] += w4.w * cv0;  acc1[q*4+3] += w4.w * cv1;
          }
          float wl = wb[24];
          acc0[24] += wl * cv0;  acc1[24] += wl * cv1;
        }
      }
    }
    __syncthreads();
  }

  #pragma unroll
  for (int k = 0; k < 25; k++) {
    float bb = __ldg(b_enc + k * 4 + ij);
    acc0[k] += bb; acc1[k] += bb;
  }

  float m0 = acc0[0], m1 = acc1[0];
  #pragma unroll
  for (int k = 1; k < 25; k++) { m0 = fmaxf(m0, acc0[k]); m1 = fmaxf(m1, acc1[k]); }
  float s0 = 0.f, s1 = 0.f;
  #pragma unroll
  for (int k = 0; k < 25; k++) {
    acc0[k] = __expf(acc0[k] - m0); s0 += acc0[k];
    acc1[k] = __expf(acc1[k] - m1); s1 += acc1[k];
  }
  float inv0 = 1.0f / s0, inv1 = 1.0f / s1;

  int p0 = (h0 + r) * W + w0 + c0;
  float* mp0 = g_mask + (size_t)(n * HW + p0) * MASK_STRIDE + ij * 28;
  float* mp1 = mp0 + MASK_STRIDE;
  #pragma unroll
  for (int k = 0; k < 25; k++) {
    mp0[k] = acc0[k] * inv0;
    mp1[k] = acc1[k] * inv1;
  }
}

// ---------------------------------------------------------------------------
// Kernel 3 (v5): CARAFE reassembly.
// vs v4: SINGLE xs buffer (double-buffer's concurrent staging live-set was
// what spilled at the 84-reg cap). launch_bounds(256,3) -> 3 blocks/SM,
// 24 warps; compute live-set ~60 regs fits 84 without spill.
// Float4 mask staging + hoisted staging addressing kept.
// ---------------------------------------------------------------------------
#define XS_STRIDE 148

__global__ void __launch_bounds__(256, 3) reassemble_kernel(
    const float* __restrict__ x,
    float* __restrict__ out) {
  __shared__ float ms[64 * MASK_STRIDE];       // 29.7 KB
  __shared__ float xs[8 * XS_STRIDE];          // 4.7 KB

  int tid = threadIdx.x;
  int cg  = tid & 3;
  int pix = tid >> 2;
  int r = pix >> 3, cl = pix & 7;

  int b    = blockIdx.x;          // 1024 blocks
  int cgrp = b & 3;               // 64-channel group
  int t    = (b >> 2) & 63;
  int n    = b >> 8;
  int h0 = (t >> 3) * 8, w0 = (t & 7) * 8;

  // ---- hoisted staging addressing: warp = local channel, lane = slot ----
  int chl  = tid >> 5;            // 0..7
  int slot = tid & 31;
  int goff[5];
  unsigned lmask = 0;             // load valid (inside image)
  unsigned smask = 0;             // store valid (inside 144-cell tile)
  #pragma unroll
  for (int q = 0; q < 5; q++) {
    int pos = slot + q * 32;
    int yy = pos / 12, xx = pos - yy * 12;
    int gh = h0 - 2 + yy, gw = w0 - 2 + xx;
    bool in_tile = pos < 144;
    bool v = in_tile && gh >= 0 && gh < H && gw >= 0 && gw < W;
    goff[q] = gh * W + gw;
    if (v) lmask |= (1u << q);
    if (in_tile) smask |= (1u << q);
  }
  int sbase = chl * XS_STRIDE + slot;
  const float* xrow = x + ((size_t)(n * C_IN + cgrp * 64 + chl)) * HW;

  // ---- stage mask tile once (float4; 464B pixel stride = 29x16 aligned) ----
  {
    float4* msd = (float4*)ms;
    for (int i = tid; i < 64 * 29; i += 256) {
      int pp  = i / 29;
      int off = i - pp * 29;
      int p = (h0 + (pp >> 3)) * W + w0 + (pp & 7);
      msd[i] = ((const float4*)(g_mask + (size_t)(n * HW + p) * MASK_STRIDE))[off];
    }
  }

  for (int cc = 0; cc < 8; cc++) {
    if (cc > 0) __syncthreads();     // protect xs overwrite
    {
      const float* xp = xrow + (size_t)cc * 8 * HW;
      #pragma unroll
      for (int q = 0; q < 5; q++) {
        if (smask >> q & 1) {
          float v = (lmask >> q & 1) ? __ldg(xp + goff[q]) : 0.f;
          xs[sbase + q * 32] = v;
        }
      }
    }
    __syncthreads();

    #pragma unroll
    for (int s = 0; s < 2; s++) {
      int ch = cg * 2 + s;
      float xw[25];
      #pragma unroll
      for (int dy = 0; dy < 5; dy++)
        #pragma unroll
        for (int dx = 0; dx < 5; dx++)
          xw[dy * 5 + dx] = xs[ch * XS_STRIDE + (r + dy) * 12 + cl + dx];

      float res[4];
      #pragma unroll
      for (int ij2 = 0; ij2 < 4; ij2++) {
        const float* mb = ms + pix * MASK_STRIDE + ij2 * 28;
        const float4* mb4 = (const float4*)mb;
        float a = 0.f;
        #pragma unroll
        for (int q = 0; q < 6; q++) {
          float4 m4 = mb4[q];
          a += m4.x * xw[q*4+0] + m4.y * xw[q*4+1]
             + m4.z * xw[q*4+2] + m4.w * xw[q*4+3];
        }
        a += mb[24] * xw[24];
        res[ij2] = a;
      }

      int c_glob = cgrp * 64 + cc * 8 + ch;
      float* ob = out + ((size_t)(n * C_IN + c_glob) * 128 + 2 * (h0 + r)) * 128
                      + 2 * (w0 + cl);
      ((float2*)ob)[0]         = make_float2(res[0], res[1]);
      ((float2*)(ob + 128))[0] = make_float2(res[2], res[3]);
    }
  }
}

// ---------------------------------------------------------------------------
extern "C" void kernel_launch(void* const* d_in, const int* in_sizes, int n_in,
                              void* d_out, int out_size) {
  const float* x      = (const float*)d_in[0];
  const float* w_comp = (const float*)d_in[1];
  const float* b_comp = (const float*)d_in[2];
  const float* w_enc  = (const float*)d_in[3];
  const float* b_enc  = (const float*)d_in[4];
  float* out = (float*)d_out;

  cudaFuncSetAttribute(conv1x1_kernel,
                       cudaFuncAttributeMaxDynamicSharedMemorySize, K1_SMEM);
  cudaFuncSetAttribute(conv3x3_softmax_kernel,
                       cudaFuncAttributeMaxDynamicSharedMemorySize,
                       (WS_FLOATS + CT_FLOATS) * 4);

  transpose_wenc_kernel<<<225, 256>>>(w_enc);
  conv1x1_kernel<<<256, 256, K1_SMEM>>>(x, w_comp, b_comp);
  conv3x3_softmax_kernel<<<256, 128, (WS_FLOATS + CT_FLOATS) * 4>>>(b_enc);
  reassemble_kernel<<<1024, 256>>>(x, out);
}

// round 11
// speedup vs baseline: 1.3245x; 1.3245x over previous
#include <cuda_runtime.h>

// Problem constants
#define N_IMG 4
#define C_IN  256
#define C_MID 64
#define H     64
#define W     64
#define HW    4096
#define KK    25
#define MASK_STRIDE 116

// Scratch (device globals; no allocation allowed)
__device__ float g_comp[N_IMG * C_MID * HW];            // [n][oc][p]
__device__ float g_mask[N_IMG * HW * MASK_STRIDE];      // [n][p][ij*28+k]
__device__ float g_wenc[C_MID * 9 * 4 * 28];            // [(ic*9+tap)*4+ij][28k]

// ---------------------------------------------------------------------------
// Kernel 0: one-time transpose of w_enc into k2's smem layout.
// ---------------------------------------------------------------------------
__global__ void transpose_wenc_kernel(const float* __restrict__ w_enc) {
  int i = blockIdx.x * 256 + threadIdx.x;      // over 100*64*9 = 57600
  if (i >= 100 * 64 * 9) return;
  int tap = i % 9;
  int ic  = (i / 9) % 64;
  int e   = i / (9 * 64);
  int k   = e >> 2;
  int ij  = e & 3;
  g_wenc[((ic * 9 + tap) * 4 + ij) * 28 + k] = w_enc[i];
}

// ---------------------------------------------------------------------------
// Kernel 1 (v6, unchanged): 1x1 conv 256 -> 64.
// ---------------------------------------------------------------------------
#define WT_STR 36
#define K1_SMEM ((256 * WT_STR + 32 * 128) * 4)   // 53248 B

__global__ void __launch_bounds__(256) conv1x1_kernel(
    const float* __restrict__ x,
    const float* __restrict__ w_comp,
    const float* __restrict__ b_comp) {
  extern __shared__ float sm1[];
  float* wt = sm1;                  // [256][36]
  float* xs = sm1 + 256 * WT_STR;   // [32][128]

  int tid = threadIdx.x;
  int ocg = tid & 3;
  int pp  = tid >> 2;

  int b     = blockIdx.x;          // 256 blocks
  int oc0   = (b & 1) * 32;
  int gp0   = (b >> 1) * 128;
  int n     = gp0 >> 12;
  int pbase = gp0 & 4095;

  for (int i = tid; i < 256 * 32; i += 256) {
    int j = i >> 8;
    int c = i & 255;
    wt[c * WT_STR + j] = w_comp[(oc0 + j) * 256 + c];
  }

  const float* xb = x + (size_t)n * C_IN * HW + pbase;

  float acc[16];
  #pragma unroll
  for (int j = 0; j < 8; j++) {
    float bv = __ldg(b_comp + oc0 + ocg * 8 + j);
    acc[j] = bv; acc[8 + j] = bv;
  }

  for (int cc = 0; cc < 8; cc++) {
    __syncthreads();
    {
      int c   = tid >> 5;
      int px4 = (tid & 31) * 4;
      #pragma unroll
      for (int i2 = 0; i2 < 4; i2++) {
        int ch = c + i2 * 8;
        float4 v = *(const float4*)(xb + (cc * 32 + ch) * HW + px4);
        *(float4*)(xs + ch * 128 + px4) = v;
      }
    }
    __syncthreads();

    #pragma unroll 8
    for (int c = 0; c < 32; c++) {
      float xv0 = xs[c * 128 + 2 * pp];
      float xv1 = xs[c * 128 + 2 * pp + 1];
      const float4* wr =
          (const float4*)(wt + (cc * 32 + c) * WT_STR + ocg * 8);
      float4 w0 = wr[0], w1 = wr[1];
      acc[0]  += w0.x * xv0;  acc[8]  += w0.x * xv1;
      acc[1]  += w0.y * xv0;  acc[9]  += w0.y * xv1;
      acc[2]  += w0.z * xv0;  acc[10] += w0.z * xv1;
      acc[3]  += w0.w * xv0;  acc[11] += w0.w * xv1;
      acc[4]  += w1.x * xv0;  acc[12] += w1.x * xv1;
      acc[5]  += w1.y * xv0;  acc[13] += w1.y * xv1;
      acc[6]  += w1.z * xv0;  acc[14] += w1.z * xv1;
      acc[7]  += w1.w * xv0;  acc[15] += w1.w * xv1;
    }
  }

  float* ob = g_comp + ((size_t)n * C_MID + oc0 + ocg * 8) * HW + pbase + 2 * pp;
  #pragma unroll
  for (int j = 0; j < 8; j++)
    *(float2*)(ob + j * HW) = make_float2(acc[j], acc[8 + j]);
}

// ---------------------------------------------------------------------------
// Kernel 2 (v4, unchanged): 3x3 conv + pixel-shuffle softmax.
// ---------------------------------------------------------------------------
#define K2_ICC 16
#define CT_ROW 12
#define WS_FLOATS (K2_ICC * 9 * 4 * 28)      // 16128
#define CT_FLOATS (K2_ICC * 10 * CT_ROW)     // 1920

__global__ void __launch_bounds__(128) conv3x3_softmax_kernel(
    const float* __restrict__ b_enc) {
  extern __shared__ float sm[];
  float* ws = sm;
  float* ct = sm + WS_FLOATS;

  int tid = threadIdx.x;
  int ij  = tid & 3;
  int tp  = tid >> 2;
  int r   = tp >> 2;
  int c0  = (tp & 3) * 2;

  int b  = blockIdx.x;
  int n  = b >> 6;
  int t  = b & 63;
  int h0 = (t >> 3) * 8;
  int w0 = (t & 7) * 8;

  float acc0[25], acc1[25];
  #pragma unroll
  for (int k = 0; k < 25; k++) { acc0[k] = 0.f; acc1[k] = 0.f; }

  for (int icc = 0; icc < C_MID / K2_ICC; icc++) {
    int ic0 = icc * K2_ICC;
    {
      const float4* src = (const float4*)(g_wenc + icc * WS_FLOATS);
      float4* dst = (float4*)ws;
      for (int i = tid; i < WS_FLOATS / 4; i += 128) dst[i] = src[i];
    }
    for (int i = tid; i < CT_FLOATS; i += 128) {
      int xx  = i % CT_ROW;
      int yy  = (i / CT_ROW) % 10;
      int icl = i / (10 * CT_ROW);
      int gh = h0 - 1 + yy, gw = w0 - 1 + xx;
      float v = 0.f;
      if (gh >= 0 && gh < H && gw >= 0 && gw < W)
        v = g_comp[((size_t)(n * C_MID + ic0 + icl) << 12) + gh * W + gw];
      ct[(icl * 10 + yy) * CT_ROW + xx] = v;
    }
    __syncthreads();

    for (int icl = 0; icl < K2_ICC; icl++) {
      #pragma unroll
      for (int ty = 0; ty < 3; ty++) {
        #pragma unroll
        for (int tx = 0; tx < 3; tx++) {
          float cv0 = ct[(icl * 10 + r + ty) * CT_ROW + c0 + tx];
          float cv1 = ct[(icl * 10 + r + ty) * CT_ROW + c0 + 1 + tx];
          const float* wb = ws + ((icl * 9 + ty * 3 + tx) * 4 + ij) * 28;
          const float4* wb4 = (const float4*)wb;
          #pragma unroll
          for (int q = 0; q < 6; q++) {
            float4 w4 = wb4[q];
            acc0[q*4+0] += w4.x * cv0;  acc1[q*4+0] += w4.x * cv1;
            acc0[q*4+1] += w4.y * cv0;  acc1[q*4+1] += w4.y * cv1;
            acc0[q*4+2] += w4.z * cv0;  acc1[q*4+2] += w4.z * cv1;
            acc0[q*4+3] += w4.w * cv0;  acc1[q*4+3] += w4.w * cv1;
          }
          float wl = wb[24];
          acc0[24] += wl * cv0;  acc1[24] += wl * cv1;
        }
      }
    }
    __syncthreads();
  }

  #pragma unroll
  for (int k = 0; k < 25; k++) {
    float bb = __ldg(b_enc + k * 4 + ij);
    acc0[k] += bb; acc1[k] += bb;
  }

  float m0 = acc0[0], m1 = acc1[0];
  #pragma unroll
  for (int k = 1; k < 25; k++) { m0 = fmaxf(m0, acc0[k]); m1 = fmaxf(m1, acc1[k]); }
  float s0 = 0.f, s1 = 0.f;
  #pragma unroll
  for (int k = 0; k < 25; k++) {
    acc0[k] = __expf(acc0[k] - m0); s0 += acc0[k];
    acc1[k] = __expf(acc1[k] - m1); s1 += acc1[k];
  }
  float inv0 = 1.0f / s0, inv1 = 1.0f / s1;

  int p0 = (h0 + r) * W + w0 + c0;
  float* mp0 = g_mask + (size_t)(n * HW + p0) * MASK_STRIDE + ij * 28;
  float* mp1 = mp0 + MASK_STRIDE;
  #pragma unroll
  for (int k = 0; k < 25; k++) {
    mp0[k] = acc0[k] * inv0;
    mp1[k] = acc1[k] * inv1;
  }
}

// ---------------------------------------------------------------------------
// Kernel 3 (v6): CARAFE reassembly = R8's proven config (NO reg cap,
// double-buffered xs, 128 regs / 2 blocks/SM) + float4 mask staging.
// The (256,3) cap experiments (R9/R10) showed the compute live-set spills
// below ~128 regs (L2 12%->39%); cap removed.
// ---------------------------------------------------------------------------
#define XS_STRIDE 148

__global__ void __launch_bounds__(256) reassemble_kernel(
    const float* __restrict__ x,
    float* __restrict__ out) {
  __shared__ float ms[64 * MASK_STRIDE];       // 29.7 KB
  __shared__ float xs[2][8 * XS_STRIDE];       // 2 x 4.7 KB

  int tid = threadIdx.x;
  int cg  = tid & 3;
  int pix = tid >> 2;
  int r = pix >> 3, cl = pix & 7;

  int b    = blockIdx.x;          // 1024 blocks
  int cgrp = b & 3;               // 64-channel group
  int t    = (b >> 2) & 63;
  int n    = b >> 8;
  int h0 = (t >> 3) * 8, w0 = (t & 7) * 8;

  // ---- hoisted staging addressing: warp = local channel, lane = slot ----
  int chl  = tid >> 5;            // 0..7
  int slot = tid & 31;
  int goff[5];
  unsigned lmask = 0;             // load valid (inside image)
  unsigned smask = 0;             // store valid (inside 144-cell tile)
  #pragma unroll
  for (int q = 0; q < 5; q++) {
    int pos = slot + q * 32;
    int yy = pos / 12, xx = pos - yy * 12;
    int gh = h0 - 2 + yy, gw = w0 - 2 + xx;
    bool in_tile = pos < 144;
    bool v = in_tile && gh >= 0 && gh < H && gw >= 0 && gw < W;
    goff[q] = gh * W + gw;
    if (v) lmask |= (1u << q);
    if (in_tile) smask |= (1u << q);
  }
  int sbase = chl * XS_STRIDE + slot;
  const float* xrow = x + ((size_t)(n * C_IN + cgrp * 64 + chl)) * HW;

  // ---- stage mask tile once (float4) + first x chunk ----
  {
    float4* msd = (float4*)ms;
    for (int i = tid; i < 64 * 29; i += 256) {
      int pp  = i / 29;
      int off = i - pp * 29;
      int p = (h0 + (pp >> 3)) * W + w0 + (pp & 7);
      msd[i] = ((const float4*)(g_mask + (size_t)(n * HW + p) * MASK_STRIDE))[off];
    }
  }
  #pragma unroll
  for (int q = 0; q < 5; q++) {
    if (smask >> q & 1) {
      float v = (lmask >> q & 1) ? __ldg(xrow + goff[q]) : 0.f;
      xs[0][sbase + q * 32] = v;
    }
  }
  __syncthreads();

  for (int cc = 0; cc < 8; cc++) {
    // stage next chunk into the other buffer (overlaps with compute)
    if (cc + 1 < 8) {
      const float* xp = xrow + (size_t)(cc + 1) * 8 * HW;
      #pragma unroll
      for (int q = 0; q < 5; q++) {
        if (smask >> q & 1) {
          float v = (lmask >> q & 1) ? __ldg(xp + goff[q]) : 0.f;
          xs[(cc + 1) & 1][sbase + q * 32] = v;
        }
      }
    }

    const float* xbuf = xs[cc & 1];
    #pragma unroll
    for (int s = 0; s < 2; s++) {
      int ch = cg * 2 + s;
      float xw[25];
      #pragma unroll
      for (int dy = 0; dy < 5; dy++)
        #pragma unroll
        for (int dx = 0; dx < 5; dx++)
          xw[dy * 5 + dx] = xbuf[ch * XS_STRIDE + (r + dy) * 12 + cl + dx];

      float res[4];
      #pragma unroll
      for (int ij2 = 0; ij2 < 4; ij2++) {
        const float* mb = ms + pix * MASK_STRIDE + ij2 * 28;
        const float4* mb4 = (const float4*)mb;
        float a = 0.f;
        #pragma unroll
        for (int q = 0; q < 6; q++) {
          float4 m4 = mb4[q];
          a += m4.x * xw[q*4+0] + m4.y * xw[q*4+1]
             + m4.z * xw[q*4+2] + m4.w * xw[q*4+3];
        }
        a += mb[24] * xw[24];
        res[ij2] = a;
      }

      int c_glob = cgrp * 64 + cc * 8 + ch;
      float* ob = out + ((size_t)(n * C_IN + c_glob) * 128 + 2 * (h0 + r)) * 128
                      + 2 * (w0 + cl);
      ((float2*)ob)[0]         = make_float2(res[0], res[1]);
      ((float2*)(ob + 128))[0] = make_float2(res[2], res[3]);
    }
    __syncthreads();
  }
}

// ---------------------------------------------------------------------------
extern "C" void kernel_launch(void* const* d_in, const int* in_sizes, int n_in,
                              void* d_out, int out_size) {
  const float* x      = (const float*)d_in[0];
  const float* w_comp = (const float*)d_in[1];
  const float* b_comp = (const float*)d_in[2];
  const float* w_enc  = (const float*)d_in[3];
  const float* b_enc  = (const float*)d_in[4];
  float* out = (float*)d_out;

  cudaFuncSetAttribute(conv1x1_kernel,
                       cudaFuncAttributeMaxDynamicSharedMemorySize, K1_SMEM);
  cudaFuncSetAttribute(conv3x3_softmax_kernel,
                       cudaFuncAttributeMaxDynamicSharedMemorySize,
                       (WS_FLOATS + CT_FLOATS) * 4);

  transpose_wenc_kernel<<<225, 256>>>(w_enc);
  conv1x1_kernel<<<256, 256, K1_SMEM>>>(x, w_comp, b_comp);
  conv3x3_softmax_kernel<<<256, 128, (WS_FLOATS + CT_FLOATS) * 4>>>(b_enc);
  reassemble_kernel<<<1024, 256>>>(x, out);
}